// round 1
// baseline (speedup 1.0000x reference)
#include <cuda_runtime.h>
#include <math.h>

#define SEQ   256
#define BATCH 64
#define XD    64
#define FEATD 256
#define DECD  256
#define HD    512
#define KTOT  (FEATD + HD)   // 768 combined reduction dim for gates

// ---------------- persistent device scratch (no allocations allowed) --------
__device__ float g_feat_tf[SEQ * BATCH * FEATD];       // 16.8 MB, precomputed tanh(x Wfx^T + b)
__device__ float g_act[2][BATCH * KTOT];               // [b][0..255]=feat(t), [256..767]=h(t); double buffered
__device__ float g_c[BATCH * HD];                      // cell state (in-place, owner-only updates)
__device__ float g_dec[BATCH * DECD];                  // tanh(h Whx^T + b)
__device__ float g_yprev[BATCH * XD];                  // y_{t-1}

__device__ __forceinline__ float sigmoidf_(float x) { return 1.0f / (1.0f + expf(-x)); }

// ---------------- K_init: zero h(0) region of act[0] and c --------------------
__global__ void k_init() {
    int i = blockIdx.x * blockDim.x + threadIdx.x;
    if (i < BATCH * KTOT) g_act[0][i] = 0.0f;
    if (i < BATCH * HD)   g_c[i] = 0.0f;
}

// ---------------- K0: teacher-forced features for all steps -------------------
// grid = SEQ*BATCH blocks (one (t,b) row), 256 threads (one feature each)
__global__ void k_feat_tf(const float* __restrict__ x,
                          const float* __restrict__ Wfx,
                          const float* __restrict__ bfx) {
    int tb = blockIdx.x;
    int f  = threadIdx.x;
    const float* xr = x + tb * XD;
    const float* w  = Wfx + f * XD;
    float s = bfx[f];
#pragma unroll
    for (int k = 0; k < XD; k++) s += xr[k] * w[k];
    g_feat_tf[tb * FEATD + f] = tanhf(s);
}

// ---------------- K1(t): dec = tanh(h Whx^T + b); feat(t) = blend -------------
// blocks 0..63  : dec, 4 cols each (64 b x 4 c = 256 threads, K=512)
// blocks 64..95 : feat, 8 cols each (2 cols per thread, K=64)
__global__ void k_pre(const float* __restrict__ Whx, const float* __restrict__ bhx,
                      const float* __restrict__ Wfx, const float* __restrict__ bfx,
                      const float* __restrict__ ms, int t) {
    int p = t & 1;
    const float* act = g_act[p];
    int blk = blockIdx.x;
    int b   = threadIdx.x & 63;
    int ci  = threadIdx.x >> 6;

    if (blk < 64) {
        int c = blk * 4 + ci;
        const float* hrow = act + b * KTOT + FEATD;
        const float* w    = Whx + c * HD;
        float s = bhx[c];
#pragma unroll 8
        for (int k = 0; k < HD; k++) s += hrow[k] * w[k];
        g_dec[b * DECD + c] = tanhf(s);
    } else {
        int j = blk - 64;
#pragma unroll
        for (int q = 0; q < 2; q++) {
            int c = j * 8 + ci * 2 + q;
            float ftf = g_feat_tf[(t * BATCH + b) * FEATD + c];
            float outv;
            if (t == 0) {
                outv = ftf;  // feat_auto == feat_tf at t=0 -> blend is identity
            } else {
                const float* yr = g_yprev + b * XD;
                const float* w  = Wfx + c * XD;
                float s = bfx[c];
#pragma unroll
                for (int k = 0; k < XD; k++) s += yr[k] * w[k];
                float fa = tanhf(s);
                float m  = ms[t];
                outv = m * fa + (1.0f - m) * ftf;
            }
            g_act[p][b * KTOT + c] = outv;
        }
    }
}

// ---------------- K2(t): gates + state update; y_t = dec Wout^T + b -----------
// blocks 0..127  : 4 h-units each (16 gate cols). Weights staged in dyn smem
//                  transposed [k][16] -> conflict-free LDS.128 per gate group.
// blocks 128..143: y_t (4 output cols each, K=256)
__global__ void k_step(const float* __restrict__ Wih, const float* __restrict__ Whh,
                       const float* __restrict__ bih, const float* __restrict__ bhh,
                       const float* __restrict__ Wout, const float* __restrict__ bout,
                       float* __restrict__ out, int t) {
    int p   = t & 1;
    int blk = blockIdx.x;

    if (blk < 128) {
        extern __shared__ float smem[];
        float* w_s = smem;                 // [KTOT][16]  = 48 KB
        float* g_s = smem + KTOT * 16;     // [BATCH][16] =  4 KB

        int n0 = blk * 4;
        // stage weights: lc = gate*4 + unit ; global row j = gate*H + n0 + unit
        for (int idx = threadIdx.x; idx < KTOT * 16; idx += blockDim.x) {
            int k  = idx >> 4;
            int lc = idx & 15;
            int gi = lc >> 2;
            int u  = lc & 3;
            int j  = gi * HD + n0 + u;
            w_s[idx] = (k < FEATD) ? Wih[j * FEATD + k] : Whh[j * HD + (k - FEATD)];
        }
        __syncthreads();

        int b  = threadIdx.x >> 2;   // 0..63
        int cg = threadIdx.x & 3;    // gate type (i,f,g,o)
        const float* actr = g_act[p] + b * KTOT;

        int jb = cg * HD + n0;
        float a0 = bih[jb + 0] + bhh[jb + 0];
        float a1 = bih[jb + 1] + bhh[jb + 1];
        float a2 = bih[jb + 2] + bhh[jb + 2];
        float a3 = bih[jb + 3] + bhh[jb + 3];

#pragma unroll 4
        for (int k = 0; k < KTOT; k += 4) {
            float4 av = *reinterpret_cast<const float4*>(&actr[k]);
            float4 w0 = *reinterpret_cast<const float4*>(&w_s[(k + 0) * 16 + cg * 4]);
            float4 w1 = *reinterpret_cast<const float4*>(&w_s[(k + 1) * 16 + cg * 4]);
            float4 w2 = *reinterpret_cast<const float4*>(&w_s[(k + 2) * 16 + cg * 4]);
            float4 w3 = *reinterpret_cast<const float4*>(&w_s[(k + 3) * 16 + cg * 4]);
            a0 += av.x * w0.x; a1 += av.x * w0.y; a2 += av.x * w0.z; a3 += av.x * w0.w;
            a0 += av.y * w1.x; a1 += av.y * w1.y; a2 += av.y * w1.z; a3 += av.y * w1.w;
            a0 += av.z * w2.x; a1 += av.z * w2.y; a2 += av.z * w2.z; a3 += av.z * w2.w;
            a0 += av.w * w3.x; a1 += av.w * w3.y; a2 += av.w * w3.z; a3 += av.w * w3.w;
        }

        g_s[b * 16 + cg * 4 + 0] = a0;
        g_s[b * 16 + cg * 4 + 1] = a1;
        g_s[b * 16 + cg * 4 + 2] = a2;
        g_s[b * 16 + cg * 4 + 3] = a3;
        __syncthreads();

        // update: thread (b, u=cg) owns unit n0+u
        {
            int u = cg;
            float i_v = g_s[b * 16 + 0  + u];
            float f_v = g_s[b * 16 + 4  + u];
            float gg  = g_s[b * 16 + 8  + u];
            float o_v = g_s[b * 16 + 12 + u];
            int n = n0 + u;
            float c_old = g_c[b * HD + n];
            float c_new = sigmoidf_(f_v) * c_old + sigmoidf_(i_v) * tanhf(gg);
            float h_new = sigmoidf_(o_v) * tanhf(c_new);
            g_c[b * HD + n] = c_new;
            g_act[p ^ 1][b * KTOT + FEATD + n] = h_new;
        }
    } else {
        // y_t = dec @ Wout^T + bout  (uses pre-update dec(h_t))
        int j2 = blk - 128;
        int b  = threadIdx.x & 63;
        int ci = threadIdx.x >> 6;
        int c  = j2 * 4 + ci;
        const float* dr = g_dec + b * DECD;
        const float* w  = Wout + c * DECD;
        float s = bout[c];
#pragma unroll 8
        for (int k = 0; k < DECD; k++) s += dr[k] * w[k];
        out[(t * BATCH + b) * XD + c] = s;
        g_yprev[b * XD + c] = s;
    }
}

// ---------------------------------------------------------------------------
extern "C" void kernel_launch(void* const* d_in, const int* in_sizes, int n_in,
                              void* d_out, int out_size) {
    const float* x    = (const float*)d_in[0];
    const float* ms   = (const float*)d_in[1];
    const float* Wfx  = (const float*)d_in[2];
    const float* bfx  = (const float*)d_in[3];
    const float* Wih  = (const float*)d_in[4];
    const float* Whh  = (const float*)d_in[5];
    const float* bih  = (const float*)d_in[6];
    const float* bhh  = (const float*)d_in[7];
    const float* Whx  = (const float*)d_in[8];
    const float* bhx  = (const float*)d_in[9];
    const float* Wout = (const float*)d_in[10];
    const float* bout = (const float*)d_in[11];
    float* out = (float*)d_out;

    const int smem_k2 = (KTOT * 16 + BATCH * 16) * sizeof(float);  // 53248 B
    static bool attr_set = false;
    if (!attr_set) {
        cudaFuncSetAttribute(k_step, cudaFuncAttributeMaxDynamicSharedMemorySize, smem_k2);
        attr_set = true;
    }

    k_init<<<(BATCH * KTOT + 255) / 256, 256>>>();
    k_feat_tf<<<SEQ * BATCH, FEATD>>>(x, Wfx, bfx);

    for (int t = 0; t < SEQ; t++) {
        k_pre<<<96, 256>>>(Whx, bhx, Wfx, bfx, ms, t);
        k_step<<<144, 256, smem_k2>>>(Wih, Whh, bih, bhh, Wout, bout, out, t);
    }
}

// round 2
// speedup vs baseline: 2.2294x; 2.2294x over previous
#include <cuda_runtime.h>
#include <math.h>

#define SEQ   256
#define BATCH 64
#define XD    64
#define FEATD 256
#define DECD  256
#define HD    512
#define KTOT  (FEATD + HD)   // 768
#define NG    128            // gate blocks
#define NF    8              // feat/output blocks
#define NB    (NG + NF)      // 136 total (<= 148 SMs -> all co-resident)

// ---------------- persistent device scratch ---------------------------------
__device__ float g_feat_tf[SEQ * BATCH * FEATD];   // precomputed teacher-forced feats
__device__ float g_act[2][BATCH * KTOT];           // [feat(256) | h(512)] double buffered
__device__ float g_dec[BATCH * DECD];
__device__ float g_yprev[BATCH * XD];
__device__ unsigned int g_bar_ct;

__device__ __forceinline__ float sig_(float x) { return 1.0f / (1.0f + expf(-x)); }

// software grid barrier (monotonic counter; reset per launch by k_init)
__device__ __forceinline__ void gsync(unsigned int target) {
    __syncthreads();
    if (threadIdx.x == 0) {
        __threadfence();
        atomicAdd(&g_bar_ct, 1u);
        while (*(volatile unsigned int*)&g_bar_ct < target) __nanosleep(64);
    }
    __syncthreads();
}

// ---------------- k_init: zero act[0] h-part, reset barrier ------------------
__global__ void k_init() {
    int i = blockIdx.x * blockDim.x + threadIdx.x;
    if (i == 0) g_bar_ct = 0u;
    if (i < BATCH * KTOT) g_act[0][i] = 0.0f;
}

// ---------------- k_feat_tf: all teacher-forced features (one shot) ----------
__global__ void k_feat_tf(const float* __restrict__ x,
                          const float* __restrict__ Wfx,
                          const float* __restrict__ bfx) {
    int tb = blockIdx.x;
    int f  = threadIdx.x;
    const float* xr = x + tb * XD;
    const float* w  = Wfx + f * XD;
    float s = bfx[f];
#pragma unroll
    for (int k = 0; k < XD; k++) s += xr[k] * w[k];
    g_feat_tf[tb * FEATD + f] = tanhf(s);
}

// ---------------- persistent kernel: all 256 steps ---------------------------
// blocks 0..127 (G): phase1 dec (2 cols each), phase2 gates (16 gate cols = 4 units)
// blocks 128..135 (F): phase1 feat blend (32 cols each), phase2 y_t (8 cols each)
__global__ void __launch_bounds__(256, 1)
k_persist(const float* __restrict__ Wih, const float* __restrict__ Whh,
          const float* __restrict__ bih, const float* __restrict__ bhh,
          const float* __restrict__ Whx, const float* __restrict__ bhx,
          const float* __restrict__ Wfx, const float* __restrict__ bfx,
          const float* __restrict__ Wout, const float* __restrict__ bout,
          const float* __restrict__ ms, float* __restrict__ out) {
    extern __shared__ float smem[];
    const int blk = blockIdx.x;
    const int tid = threadIdx.x;

    if (blk < NG) {
        // ======================= G block ====================================
        float* w_s   = smem;                     // [KTOT][16] gate weights, 48KB
        float* wdec  = smem + KTOT * 16;         // [2][HD] dec weights, 4KB
        float* g_ex  = wdec + 2 * HD;            // [64][16] gate exchange, 4KB

        const int n0 = blk * 4;                  // first h-unit owned
        // stage gate weights once: column lc = gate*4 + unit
        for (int idx = tid; idx < KTOT * 16; idx += 256) {
            int k  = idx >> 4;
            int lc = idx & 15;
            int gi = lc >> 2;
            int u  = lc & 3;
            int j  = gi * HD + n0 + u;
            w_s[idx] = (k < FEATD) ? Wih[j * FEATD + k] : Whh[j * HD + (k - FEATD)];
        }
        // stage dec weight rows 2*blk, 2*blk+1 (contiguous)
        for (int idx = tid; idx < 2 * HD; idx += 256)
            wdec[idx] = Whx[2 * blk * HD + idx];

        const int b  = tid >> 2;                 // batch 0..63
        const int cg = tid & 3;                  // gate (i,f,g,o)
        const int jb = cg * HD + n0;
        const float bb0 = bih[jb + 0] + bhh[jb + 0];
        const float bb1 = bih[jb + 1] + bhh[jb + 1];
        const float bb2 = bih[jb + 2] + bhh[jb + 2];
        const float bb3 = bih[jb + 3] + bhh[jb + 3];
        float c_reg = 0.0f;                      // cell state for (b, unit n0+cg)
        __syncthreads();

        for (int t = 0; t < SEQ; t++) {
            const int p = t & 1;
            // ---- phase 1: dec cols 2*blk, 2*blk+1 --------------------------
            if (tid < 128) {
                int b1 = tid & 63;
                int ci = tid >> 6;
                const float4* hv = (const float4*)(&g_act[p][b1 * KTOT + FEATD]);
                const float4* wv = (const float4*)(wdec + ci * HD);
                float s0 = 0.f, s1 = 0.f, s2 = 0.f, s3 = 0.f;
#pragma unroll 8
                for (int k = 0; k < HD / 4; k++) {
                    float4 h4 = __ldcg(hv + k);
                    float4 w4 = wv[k];
                    s0 += h4.x * w4.x; s1 += h4.y * w4.y;
                    s2 += h4.z * w4.z; s3 += h4.w * w4.w;
                }
                int c = 2 * blk + ci;
                float s = (s0 + s1) + (s2 + s3) + bhx[c];
                __stcg(&g_dec[b1 * DECD + c], tanhf(s));
            }
            gsync((unsigned)(2 * t + 1) * NB);

            // ---- phase 2: gates ---------------------------------------------
            float a0 = bb0, a1 = bb1, a2 = bb2, a3 = bb3;
            const float4* actv = (const float4*)(&g_act[p][b * KTOT]);
#pragma unroll 4
            for (int kk = 0; kk < KTOT / 4; kk++) {
                float4 av = __ldcg(actv + kk);
                int kb = kk * 4;
                float4 w0 = *(const float4*)&w_s[(kb + 0) * 16 + cg * 4];
                float4 w1 = *(const float4*)&w_s[(kb + 1) * 16 + cg * 4];
                float4 w2 = *(const float4*)&w_s[(kb + 2) * 16 + cg * 4];
                float4 w3 = *(const float4*)&w_s[(kb + 3) * 16 + cg * 4];
                a0 += av.x * w0.x; a1 += av.x * w0.y; a2 += av.x * w0.z; a3 += av.x * w0.w;
                a0 += av.y * w1.x; a1 += av.y * w1.y; a2 += av.y * w1.z; a3 += av.y * w1.w;
                a0 += av.z * w2.x; a1 += av.z * w2.y; a2 += av.z * w2.z; a3 += av.z * w2.w;
                a0 += av.w * w3.x; a1 += av.w * w3.y; a2 += av.w * w3.z; a3 += av.w * w3.w;
            }
            g_ex[b * 16 + cg * 4 + 0] = a0;
            g_ex[b * 16 + cg * 4 + 1] = a1;
            g_ex[b * 16 + cg * 4 + 2] = a2;
            g_ex[b * 16 + cg * 4 + 3] = a3;
            __syncthreads();
            {
                int u = cg;                      // this thread owns unit n0+u
                float i_v = g_ex[b * 16 + 0  + u];
                float f_v = g_ex[b * 16 + 4  + u];
                float gg  = g_ex[b * 16 + 8  + u];
                float o_v = g_ex[b * 16 + 12 + u];
                float c_new = sig_(f_v) * c_reg + sig_(i_v) * tanhf(gg);
                float h_new = sig_(o_v) * tanhf(c_new);
                c_reg = c_new;
                __stcg(&g_act[p ^ 1][b * KTOT + FEATD + n0 + u], h_new);
            }
            gsync((unsigned)(2 * t + 2) * NB);
        }
    } else {
        // ======================= F block ====================================
        const int f = blk - NG;
        float* wfx_s  = smem;                    // [32][64]  feat weight slice, 8KB
        float* wout_s = smem + 32 * XD;          // [8][256]  out weight slice, 8KB
        for (int idx = tid; idx < 32 * XD; idx += 256)
            wfx_s[idx] = Wfx[f * 32 * XD + idx];
        for (int idx = tid; idx < 8 * DECD; idx += 256)
            wout_s[idx] = Wout[f * 8 * DECD + idx];

        const int b  = tid & 63;
        const int ci = tid >> 6;                 // 0..3
        __syncthreads();

        for (int t = 0; t < SEQ; t++) {
            const int p = t & 1;
            // ---- phase 1: feat blend (cols f*32 .. f*32+31) ----------------
            {
                float yr[XD];
                if (t > 0) {
                    const float4* yv = (const float4*)(&g_yprev[b * XD]);
#pragma unroll
                    for (int k = 0; k < XD / 4; k++) {
                        float4 v = __ldcg(yv + k);
                        yr[4 * k] = v.x; yr[4 * k + 1] = v.y;
                        yr[4 * k + 2] = v.z; yr[4 * k + 3] = v.w;
                    }
                }
                float m = ms[t];
#pragma unroll
                for (int q = 0; q < 8; q++) {
                    int cl = ci * 8 + q;
                    int c  = f * 32 + cl;
                    float ftf = __ldg(&g_feat_tf[(t * BATCH + b) * FEATD + c]);
                    float outv;
                    if (t == 0) {
                        outv = ftf;
                    } else {
                        float s = bfx[c];
                        const float* w = wfx_s + cl * XD;
#pragma unroll
                        for (int k = 0; k < XD; k++) s += yr[k] * w[k];
                        float fa = tanhf(s);
                        outv = m * fa + (1.0f - m) * ftf;
                    }
                    __stcg(&g_act[p][b * KTOT + c], outv);
                }
            }
            gsync((unsigned)(2 * t + 1) * NB);

            // ---- phase 2: y_t (cols f*8 .. f*8+7) --------------------------
            {
                const float4* dv = (const float4*)(&g_dec[b * DECD]);
#pragma unroll
                for (int q = 0; q < 2; q++) {
                    int cl = ci * 2 + q;
                    int c  = f * 8 + cl;
                    const float4* wv = (const float4*)(wout_s + cl * DECD);
                    float s0 = 0.f, s1 = 0.f, s2 = 0.f, s3 = 0.f;
#pragma unroll 8
                    for (int k = 0; k < DECD / 4; k++) {
                        float4 d4 = __ldcg(dv + k);
                        float4 w4 = wv[k];
                        s0 += d4.x * w4.x; s1 += d4.y * w4.y;
                        s2 += d4.z * w4.z; s3 += d4.w * w4.w;
                    }
                    float s = (s0 + s1) + (s2 + s3) + bout[c];
                    out[(t * BATCH + b) * XD + c] = s;
                    __stcg(&g_yprev[b * XD + c], s);
                }
            }
            gsync((unsigned)(2 * t + 2) * NB);
        }
    }
}

// ---------------------------------------------------------------------------
extern "C" void kernel_launch(void* const* d_in, const int* in_sizes, int n_in,
                              void* d_out, int out_size) {
    const float* x    = (const float*)d_in[0];
    const float* ms   = (const float*)d_in[1];
    const float* Wfx  = (const float*)d_in[2];
    const float* bfx  = (const float*)d_in[3];
    const float* Wih  = (const float*)d_in[4];
    const float* Whh  = (const float*)d_in[5];
    const float* bih  = (const float*)d_in[6];
    const float* bhh  = (const float*)d_in[7];
    const float* Whx  = (const float*)d_in[8];
    const float* bhx  = (const float*)d_in[9];
    const float* Wout = (const float*)d_in[10];
    const float* bout = (const float*)d_in[11];
    float* out = (float*)d_out;

    const int smem_p = (KTOT * 16 + 2 * HD + 64 * 16) * sizeof(float);  // 57344 B
    static bool attr_set = false;
    if (!attr_set) {
        cudaFuncSetAttribute(k_persist, cudaFuncAttributeMaxDynamicSharedMemorySize, smem_p);
        attr_set = true;
    }

    k_init<<<(BATCH * KTOT + 255) / 256, 256>>>();
    k_feat_tf<<<SEQ * BATCH, FEATD>>>(x, Wfx, bfx);
    k_persist<<<NB, 256, smem_p>>>(Wih, Whh, bih, bhh, Whx, bhx,
                                   Wfx, bfx, Wout, bout, ms, out);
}